// round 2
// baseline (speedup 1.0000x reference)
#include <cuda_runtime.h>

// predictor_interp2d: nearest-neighbor gather from N=1024 points onto a 256x256 grid.
// d_in[0] = R_pc  [B=2, C=4, N=1024] float32
// d_in[1] = XY_pc [B=2, 2, N=1024]   float32
// d_out   = R_grd [B=2, C=4, 256, 256] float32

#define HGT   256
#define WIDG  256
#define NPTS  1024
#define NCH   4
#define GRID_CELLS (HGT * WIDG)        // 65536 per batch
#define THREADS 512
#define TILES_PER_BATCH 64             // 65536 / (THREADS * 2 cells/thread)

__global__ __launch_bounds__(THREADS, 1)
void nn_argmin_gather_kernel(const float* __restrict__ R,
                             const float* __restrict__ XY,
                             float* __restrict__ out) {
    __shared__ float4 pts[NPTS];       // {px, py, px^2+py^2, unused}

    const int t    = threadIdx.x;
    const int b    = blockIdx.x >> 6;          // 64 tiles per batch
    const int tile = blockIdx.x & 63;

    // Stage points for this batch into shared memory, precomputing s = px*px + py*py
    // with the reference's rounding order (mul, mul, add — elementwise, no contraction).
    const float* xy = XY + b * (2 * NPTS);
    #pragma unroll
    for (int i = t; i < NPTS; i += THREADS) {
        float px = xy[i];
        float py = xy[NPTS + i];
        float s  = __fadd_rn(__fmul_rn(px, px), __fmul_rn(py, py));
        pts[i] = make_float4(px, py, s, 0.0f);
    }
    __syncthreads();

    // Each thread owns 2 grid cells (consecutive 512-apart for coalesced stores).
    const int cell0 = tile * (THREADS * 2);
    const int c0 = cell0 + t;
    const int c1 = cell0 + t + THREADS;

    const float inv = 1.0f / 256.0f;   // exact power of two: (x+0.5)*inv == (x+0.5)/256
    const float gx0 = ((float)(c0 & 255) + 0.5f) * inv;
    const float gy0 = ((float)(c0 >> 8)  + 0.5f) * inv;
    const float gx1 = ((float)(c1 & 255) + 0.5f) * inv;
    const float gy1 = ((float)(c1 >> 8)  + 0.5f) * inv;

    float best0 = 3.402823466e38f;
    float best1 = 3.402823466e38f;
    int   idx0  = 0;
    int   idx1  = 0;

    // Argmin scan. Rounding order matches the reference's K=2 GEMM accumulation:
    //   dot = fmaf(gy, py, rn(gx*px))          [k=0 from zero, k=1 fused]
    //   d2  = fmaf(-2, dot, s) == rn(s - 2*dot) [-2*dot exact]
    // Strict '<' with ascending i keeps the FIRST minimum (jnp.argmin semantics).
    #pragma unroll 4
    for (int i = 0; i < NPTS; ++i) {
        const float4 p = pts[i];

        const float dot0 = __fmaf_rn(p.y, gy0, __fmul_rn(p.x, gx0));
        const float d0   = __fmaf_rn(-2.0f, dot0, p.z);
        const float dot1 = __fmaf_rn(p.y, gy1, __fmul_rn(p.x, gx1));
        const float d1   = __fmaf_rn(-2.0f, dot1, p.z);

        if (d0 < best0) idx0 = i;
        best0 = fminf(best0, d0);
        if (d1 < best1) idx1 = i;
        best1 = fminf(best1, d1);
    }

    // Gather 4 channels per cell; R is tiny (16 KB) -> L1/L2 resident.
    const float* Rb = R   + b * (NCH * NPTS);
    float*       ob = out + b * (NCH * GRID_CELLS);
    #pragma unroll
    for (int c = 0; c < NCH; ++c) {
        ob[c * GRID_CELLS + c0] = Rb[c * NPTS + idx0];
        ob[c * GRID_CELLS + c1] = Rb[c * NPTS + idx1];
    }
}

extern "C" void kernel_launch(void* const* d_in, const int* in_sizes, int n_in,
                              void* d_out, int out_size) {
    const float* R  = (const float*)d_in[0];   // [2,4,1024]
    const float* XY = (const float*)d_in[1];   // [2,2,1024]
    float* out = (float*)d_out;                // [2,4,256,256]

    dim3 grid(2 * TILES_PER_BATCH);            // 128 blocks, one wave on 148 SMs
    dim3 block(THREADS);
    nn_argmin_gather_kernel<<<grid, block>>>(R, XY, out);
}

// round 3
// speedup vs baseline: 1.9968x; 1.9968x over previous
#include <cuda_runtime.h>

// predictor_interp2d: nearest-neighbor gather from N=1024 points onto a 256x256 grid.
// d_in[0] = R_pc  [B=2, C=4, N=1024] float32
// d_in[1] = XY_pc [B=2, 2, N=1024]   float32
// d_out   = R_grd [B=2, C=4, 256, 256] float32
//
// Two-kernel pipeline:
//   1) build_bins: bin the 1024 points of each batch into a 16x16 CSR structure
//      (bin width 1/16; one 256x256 grid bin covers 16x16 cells).
//   2) query: per-cell expanding-ring nearest-neighbor search with a rounding-safe
//      termination bound. Candidate d2 uses the EXACT reference arithmetic
//      (s = rn(rn(px^2)+rn(py^2)); dot = fmaf(py,gy, rn(px*gx)); d2 = fmaf(-2,dot,s)),
//      and exact-value ties resolve to the smallest point index == jnp.argmin.

#define NPTS  1024
#define NB    16           // bins per axis
#define BINW  0.0625f      // 1/16

__device__ float4 g_pts[2][NPTS];   // {px, py, s, index-as-bits} reordered by bin
__device__ int    g_off[2][NB*NB + 1];

__global__ __launch_bounds__(512, 1)
void build_bins(const float* __restrict__ XY) {
    const int b = blockIdx.x;
    const int t = threadIdx.x;
    const float* xy = XY + b * (2 * NPTS);

    __shared__ int cnt[NB*NB];
    __shared__ int scan[NB*NB];
    __shared__ int offx[NB*NB + 1];

    if (t < 256) cnt[t] = 0;
    __syncthreads();

    float px[2], py[2]; int bin[2];
    #pragma unroll
    for (int j = 0; j < 2; ++j) {
        const int i = t + j * 512;
        const float x = xy[i];
        const float y = xy[NPTS + i];
        int bx = min(max((int)(x * 16.0f), 0), NB - 1);
        int by = min(max((int)(y * 16.0f), 0), NB - 1);
        px[j] = x; py[j] = y; bin[j] = by * NB + bx;
        atomicAdd(&cnt[bin[j]], 1);
    }
    __syncthreads();

    // Hillis-Steele inclusive scan over 256 bin counts.
    if (t < 256) scan[t] = cnt[t];
    __syncthreads();
    for (int d = 1; d < 256; d <<= 1) {
        int v = 0;
        if (t < 256 && t >= d) v = scan[t - d];
        __syncthreads();
        if (t < 256) scan[t] += v;
        __syncthreads();
    }
    if (t < 256) offx[t + 1] = scan[t];
    if (t == 0)  offx[0] = 0;
    __syncthreads();

    if (t <= 256) g_off[b][t] = offx[t];
    if (t < 256)  cnt[t] = 0;          // reuse as scatter cursor
    __syncthreads();

    #pragma unroll
    for (int j = 0; j < 2; ++j) {
        const int i = t + j * 512;
        const int pos = offx[bin[j]] + atomicAdd(&cnt[bin[j]], 1);
        // s with the reference's rounding order (mul, mul, add)
        const float s = __fadd_rn(__fmul_rn(px[j], px[j]), __fmul_rn(py[j], py[j]));
        g_pts[b][pos] = make_float4(px[j], py[j], s, __int_as_float(i));
    }
}

__global__ __launch_bounds__(512, 1)
void query_nn(const float* __restrict__ R, float* __restrict__ out) {
    const int t    = threadIdx.x;
    const int bid  = blockIdx.x;
    const int b    = bid >> 7;                  // 128 blocks per batch
    const int cell = (bid & 127) * 512 + t;     // 0..65535
    const int cx = cell & 255;
    const int cy = cell >> 8;

    const float inv = 1.0f / 256.0f;
    const float gx = ((float)cx + 0.5f) * inv;
    const float gy = ((float)cy + 0.5f) * inv;
    const float g2 = gx * gx + gy * gy;         // geometry bound only (rounding-free req.)

    const int bx = cx >> 4;
    const int by = cy >> 4;

    const float4* __restrict__ pts = g_pts[b];
    const int*    __restrict__ off = g_off[b];

    float best = 3.402823466e38f;
    int   bi   = 0;

    for (int r = 0; r < NB; ++r) {
        if (r > 0) {
            // Distance from (gx,gy) to the boundary of the already-scanned bin square
            // [bx-(r-1), bx+(r-1)] x [by-(r-1), by+(r-1)]; faces at the domain edge
            // have no bins beyond them and are excluded.
            const float fL = (bx - (r - 1) >= 1)      ? (gx - (float)(bx - (r - 1)) * BINW) : 1e30f;
            const float fR = (bx + (r - 1) <= NB - 2) ? ((float)(bx + r) * BINW - gx)       : 1e30f;
            const float fB = (by - (r - 1) >= 1)      ? (gy - (float)(by - (r - 1)) * BINW) : 1e30f;
            const float fT = (by + (r - 1) <= NB - 2) ? ((float)(by + r) * BINW - gy)       : 1e30f;
            const float f  = fminf(fminf(fL, fR), fminf(fB, fT));
            // Any unscanned point has true dist^2 >= f^2, so computed d2 >= f^2 - g2 - eps.
            // Break only when that strictly exceeds best (slack 1e-4 >> rounding eps ~2e-6),
            // which also forbids unscanned exact ties. (f*f may overflow to inf: still breaks.)
            if (f * f > best + g2 + 1e-4f) break;
        }
        const int x0 = max(bx - r, 0), x1 = min(bx + r, NB - 1);
        const int y0 = max(by - r, 0), y1 = min(by + r, NB - 1);
        for (int yb = y0; yb <= y1; ++yb) {
            const bool yedge = (yb == by - r) || (yb == by + r);
            for (int xb = x0; xb <= x1; ++xb) {
                if (!yedge && xb != bx - r && xb != bx + r) continue;  // ring only
                const int bin = yb * NB + xb;
                const int e0 = __ldg(&off[bin]);
                const int e1 = __ldg(&off[bin + 1]);
                for (int k = e0; k < e1; ++k) {
                    const float4 p = __ldg(&pts[k]);
                    // Exact reference arithmetic (bit-matched in R2):
                    const float dot = __fmaf_rn(p.y, gy, __fmul_rn(p.x, gx));
                    const float d   = __fmaf_rn(-2.0f, dot, p.z);
                    const int   i   = __float_as_int(p.w);
                    if (d < best) { best = d; bi = i; }
                    else if (d == best && i < bi) { bi = i; }  // first-min tie rule
                }
            }
        }
    }

    const float* Rb = R   + b * (4 * NPTS);
    float*       ob = out + b * (4 * 65536);
    #pragma unroll
    for (int c = 0; c < 4; ++c)
        ob[c * 65536 + cell] = Rb[c * NPTS + bi];
}

extern "C" void kernel_launch(void* const* d_in, const int* in_sizes, int n_in,
                              void* d_out, int out_size) {
    const float* R  = (const float*)d_in[0];   // [2,4,1024]
    const float* XY = (const float*)d_in[1];   // [2,2,1024]
    float* out = (float*)d_out;                // [2,4,256,256]

    build_bins<<<2, 512>>>(XY);
    query_nn<<<256, 512>>>(R, out);
}

// round 4
// speedup vs baseline: 2.6725x; 1.3384x over previous
#include <cuda_runtime.h>

// predictor_interp2d: nearest-neighbor gather from N=1024 points onto a 256x256 grid.
// d_in[0] = R_pc  [B=2, C=4, N=1024] float32
// d_in[1] = XY_pc [B=2, 2, N=1024]   float32
// d_out   = R_grd [B=2, C=4, 256, 256] float32
//
// Pipeline:
//   1) build_bins: bin the 1024 points of each batch into a 16x16 CSR (bin = 1/16).
//   2) query_nn: one block per bin tile (16x16 cells). Block-uniform expanding-ring
//      search over smem-staged points; per-thread argmin with the EXACT reference
//      arithmetic (bit-matched in R2/R3) and first-min tie rule.

#define NPTS  1024
#define NB    16
#define BINW  0.0625f

__device__ float4 g_pts[2][NPTS];   // {px, py, s, index-as-bits} reordered by bin
__device__ int    g_off[2][NB*NB + 1];

__global__ __launch_bounds__(512, 1)
void build_bins(const float* __restrict__ XY) {
    const int b = blockIdx.x;
    const int t = threadIdx.x;
    const float* xy = XY + b * (2 * NPTS);

    __shared__ int cnt[NB*NB];
    __shared__ int scan[NB*NB];
    __shared__ int offx[NB*NB + 1];

    if (t < 256) cnt[t] = 0;
    __syncthreads();

    float px[2], py[2]; int bin[2];
    #pragma unroll
    for (int j = 0; j < 2; ++j) {
        const int i = t + j * 512;
        const float x = xy[i];
        const float y = xy[NPTS + i];
        int bx = min(max((int)(x * 16.0f), 0), NB - 1);
        int by = min(max((int)(y * 16.0f), 0), NB - 1);
        px[j] = x; py[j] = y; bin[j] = by * NB + bx;
        atomicAdd(&cnt[bin[j]], 1);
    }
    __syncthreads();

    // Hillis-Steele inclusive scan over 256 bin counts.
    if (t < 256) scan[t] = cnt[t];
    __syncthreads();
    for (int d = 1; d < 256; d <<= 1) {
        int v = 0;
        if (t < 256 && t >= d) v = scan[t - d];
        __syncthreads();
        if (t < 256) scan[t] += v;
        __syncthreads();
    }
    if (t < 256) offx[t + 1] = scan[t];
    if (t == 0)  offx[0] = 0;
    __syncthreads();

    if (t <= 256) g_off[b][t] = offx[t];
    if (t < 256)  cnt[t] = 0;          // reuse as scatter cursor
    __syncthreads();

    #pragma unroll
    for (int j = 0; j < 2; ++j) {
        const int i = t + j * 512;
        const int pos = offx[bin[j]] + atomicAdd(&cnt[bin[j]], 1);
        // s with the reference's rounding order (mul, mul, add)
        const float s = __fadd_rn(__fmul_rn(px[j], px[j]), __fmul_rn(py[j], py[j]));
        g_pts[b][pos] = make_float4(px[j], py[j], s, __int_as_float(i));
    }
}

__global__ __launch_bounds__(256, 4)
void query_nn(const float* __restrict__ R, float* __restrict__ out) {
    __shared__ float4 spts[NPTS];      // all points of this batch (16 KB)
    __shared__ int    soff[NB*NB + 1];

    const int t   = threadIdx.x;
    const int b   = blockIdx.x >> 8;           // 256 bin-tiles per batch
    const int bin = blockIdx.x & 255;
    const int bx  = bin & (NB - 1);            // block-uniform home bin
    const int by  = bin >> 4;

    // Stage points + offsets (coalesced; hides latency across 4 blocks/SM).
    #pragma unroll
    for (int i = t; i < NPTS; i += 256) spts[i] = g_pts[b][i];
    for (int i = t; i < NB*NB + 1; i += 256) soff[i] = g_off[b][i];
    __syncthreads();

    // This thread's cell inside the 16x16 tile of the home bin.
    const int lx = t & 15, ly = t >> 4;
    const int cx = bx * 16 + lx;
    const int cy = by * 16 + ly;
    const int cell = cy * 256 + cx;

    const float inv = 1.0f / 256.0f;
    const float gx = ((float)cx + 0.5f) * inv;
    const float gy = ((float)cy + 0.5f) * inv;
    const float g2 = gx * gx + gy * gy;        // geometry bound only

    float best = 3.402823466e38f;
    int   bi   = 0;

    for (int r = 0; r < NB; ++r) {
        if (r > 0) {
            // Per-thread termination bound: distance from (gx,gy) to the boundary of
            // the already-scanned bin square; domain-edge faces excluded.
            const float fL = (bx - (r - 1) >= 1)      ? (gx - (float)(bx - (r - 1)) * BINW) : 1e30f;
            const float fR = (bx + (r - 1) <= NB - 2) ? ((float)(bx + r) * BINW - gx)       : 1e30f;
            const float fB = (by - (r - 1) >= 1)      ? (gy - (float)(by - (r - 1)) * BINW) : 1e30f;
            const float fT = (by + (r - 1) <= NB - 2) ? ((float)(by + r) * BINW - gy)       : 1e30f;
            const float f  = fminf(fminf(fL, fR), fminf(fB, fT));
            // Done when every unscanned point's computed d2 strictly exceeds best
            // (slack 1e-4 >> rounding eps, so ties among unscanned are impossible;
            //  therefore scanning extra rings for block-mates can never update us).
            const int cont = !(f * f > best + g2 + 1e-4f);
            if (!__syncthreads_or(cont)) break;   // block-uniform exit
        }
        // Ring r around the block-uniform home bin: uniform control flow.
        const int x0 = max(bx - r, 0), x1 = min(bx + r, NB - 1);
        const int y0 = max(by - r, 0), y1 = min(by + r, NB - 1);
        for (int yb = y0; yb <= y1; ++yb) {
            const bool yedge = (yb == by - r) || (yb == by + r);
            const int xs = yedge ? 1 : ((bx + r <= NB - 1 && bx - r >= 0) ? (2 * r) : 1);
            for (int xb = x0; xb <= x1; ) {
                if (yedge || xb == bx - r || xb == bx + r) {
                    const int bb = yb * NB + xb;
                    const int e0 = soff[bb];
                    const int e1 = soff[bb + 1];
                    for (int k = e0; k < e1; ++k) {
                        const float4 p = spts[k];
                        // Exact reference arithmetic (bit-matched):
                        const float dot = __fmaf_rn(p.y, gy, __fmul_rn(p.x, gx));
                        const float d   = __fmaf_rn(-2.0f, dot, p.z);
                        const int   i   = __float_as_int(p.w);
                        if (d < best) { best = d; bi = i; }
                        else if (d == best && i < bi) { bi = i; }
                    }
                    xb += (yedge ? 1 : (xs > 0 ? xs : 1));
                } else {
                    ++xb;
                }
            }
        }
    }

    const float* Rb = R   + b * (4 * NPTS);
    float*       ob = out + b * (4 * 65536);
    #pragma unroll
    for (int c = 0; c < 4; ++c)
        ob[c * 65536 + cell] = Rb[c * NPTS + bi];
}

extern "C" void kernel_launch(void* const* d_in, const int* in_sizes, int n_in,
                              void* d_out, int out_size) {
    const float* R  = (const float*)d_in[0];   // [2,4,1024]
    const float* XY = (const float*)d_in[1];   // [2,2,1024]
    float* out = (float*)d_out;                // [2,4,256,256]

    build_bins<<<2, 512>>>(XY);
    query_nn<<<512, 256>>>(R, out);
}

// round 5
// speedup vs baseline: 3.5918x; 1.3440x over previous
#include <cuda_runtime.h>

// predictor_interp2d: nearest-neighbor gather from N=1024 points onto a 256x256 grid.
// d_in[0] = R_pc  [B=2, C=4, N=1024] float32
// d_in[1] = XY_pc [B=2, 2, N=1024]   float32
// d_out   = R_grd [B=2, C=4, 256, 256] float32
//
// Single fused kernel: one block per 16x16-cell bin tile (512 blocks total).
// Each block redundantly bins all 1024 points of its batch into a block-local
// 16x16 CSR in shared memory (cheap, fully parallel across blocks), then runs a
// block-uniform expanding-ring NN search. Candidate d2 uses the EXACT reference
// arithmetic (bit-matched since R2); exact ties resolve to the smallest point
// index == jnp.argmin first-min semantics, making the atomic scatter order
// irrelevant to the output.

#define NPTS  1024
#define NB    16
#define BINW  0.0625f

__global__ __launch_bounds__(256, 4)
void nn_fused(const float* __restrict__ XY,
              const float* __restrict__ R,
              float* __restrict__ out) {
    __shared__ float4 spts[NPTS];       // {px, py, s, index-as-bits}, bin-ordered
    __shared__ int    soff[NB*NB + 1];  // CSR offsets
    __shared__ int    scnt[NB*NB];      // counts, then scatter cursors
    __shared__ int    swsum[8];         // per-warp scan partials

    const int t   = threadIdx.x;
    const int b   = blockIdx.x >> 8;            // 256 bin-tiles per batch
    const int bin = blockIdx.x & 255;
    const int bx  = bin & (NB - 1);             // block-uniform home bin
    const int by  = bin >> 4;

    // ---- Phase 1: block-local binning of all 1024 points (4 per thread) ----
    const float* xy = XY + b * (2 * NPTS);
    float px[4], py[4]; int pbin[4];

    scnt[t] = 0;
    __syncthreads();
    #pragma unroll
    for (int j = 0; j < 4; ++j) {
        const int i = t + j * 256;
        const float x = xy[i];
        const float y = xy[NPTS + i];
        const int bxx = min(max((int)(x * 16.0f), 0), NB - 1);
        const int byy = min(max((int)(y * 16.0f), 0), NB - 1);
        px[j] = x; py[j] = y; pbin[j] = byy * NB + bxx;
        atomicAdd(&scnt[pbin[j]], 1);
    }
    __syncthreads();

    // Two-level exclusive scan over 256 counts (warp shfl + 8-way warp-0 scan).
    const int v = scnt[t];
    int incl = v;
    #pragma unroll
    for (int d = 1; d < 32; d <<= 1) {
        const int n = __shfl_up_sync(0xffffffffu, incl, d);
        if ((t & 31) >= d) incl += n;
    }
    if ((t & 31) == 31) swsum[t >> 5] = incl;
    __syncthreads();
    if (t < 32) {
        const int w = (t < 8) ? swsum[t] : 0;
        int iw = w;
        #pragma unroll
        for (int d = 1; d < 8; d <<= 1) {
            const int n = __shfl_up_sync(0xffffffffu, iw, d);
            if (t >= d) iw += n;
        }
        if (t < 8) swsum[t] = iw - w;           // exclusive warp base
    }
    __syncthreads();
    soff[t] = incl - v + swsum[t >> 5];         // exclusive prefix for bin t
    if (t == 0) soff[NB*NB] = NPTS;
    scnt[t] = 0;                                // reuse as scatter cursor
    __syncthreads();

    #pragma unroll
    for (int j = 0; j < 4; ++j) {
        const int i   = t + j * 256;
        const int pos = soff[pbin[j]] + atomicAdd(&scnt[pbin[j]], 1);
        // s with the reference's rounding order (mul, mul, add)
        const float s = __fadd_rn(__fmul_rn(px[j], px[j]), __fmul_rn(py[j], py[j]));
        spts[pos] = make_float4(px[j], py[j], s, __int_as_float(i));
    }
    __syncthreads();

    // ---- Phase 2: expanding-ring NN search (block-uniform control flow) ----
    const int lx = t & 15, ly = t >> 4;
    const int cx = bx * 16 + lx;
    const int cy = by * 16 + ly;
    const int cell = cy * 256 + cx;

    const float inv = 1.0f / 256.0f;
    const float gx = ((float)cx + 0.5f) * inv;
    const float gy = ((float)cy + 0.5f) * inv;
    const float g2 = gx * gx + gy * gy;         // geometry bound only

    float best = 3.402823466e38f;
    int   bi   = 0;

    #define SCAN_RANGE(E0, E1)                                                  \
        for (int k = (E0); k < (E1); ++k) {                                     \
            const float4 p = spts[k];                                           \
            const float dot = __fmaf_rn(p.y, gy, __fmul_rn(p.x, gx));           \
            const float d   = __fmaf_rn(-2.0f, dot, p.z);                       \
            const int   i   = __float_as_int(p.w);                              \
            if (d < best) { best = d; bi = i; }                                 \
            else if (d == best && i < bi) { bi = i; }                           \
        }

    for (int r = 0; r < NB; ++r) {
        if (r > 0) {
            // Per-thread bound: distance to the boundary of the scanned bin square
            // [bx-(r-1), bx+(r-1)]^2; domain-edge faces excluded. Unscanned points
            // have computed d2 >= f^2 - g2 - eps; slack 1e-4 >> eps forbids any
            // unscanned point from beating OR tying the current winner.
            const float fL = (bx - (r - 1) >= 1)      ? (gx - (float)(bx - (r - 1)) * BINW) : 1e30f;
            const float fR = (bx + (r - 1) <= NB - 2) ? ((float)(bx + r) * BINW - gx)       : 1e30f;
            const float fB = (by - (r - 1) >= 1)      ? (gy - (float)(by - (r - 1)) * BINW) : 1e30f;
            const float fT = (by + (r - 1) <= NB - 2) ? ((float)(by + r) * BINW - gy)       : 1e30f;
            const float f  = fminf(fminf(fL, fR), fminf(fB, fT));
            const int cont = !(f * f > best + g2 + 1e-4f);
            if (!__syncthreads_or(cont)) break;   // block-uniform exit
        }
        const int x0 = max(bx - r, 0), x1 = min(bx + r, NB - 1);
        const int y0 = max(by - r, 0), y1 = min(by + r, NB - 1);
        for (int yb = y0; yb <= y1; ++yb) {
            if (yb == by - r || yb == by + r) {
                // Full ring row: bins x0..x1 are CSR-contiguous -> one flat segment.
                const int e0 = soff[yb * NB + x0];
                const int e1 = soff[yb * NB + x1 + 1];
                SCAN_RANGE(e0, e1)
            } else {
                // Middle row: only the two ring columns.
                if (bx - r >= 0) {
                    const int bb = yb * NB + (bx - r);
                    SCAN_RANGE(soff[bb], soff[bb + 1])
                }
                if (bx + r <= NB - 1) {
                    const int bb = yb * NB + (bx + r);
                    SCAN_RANGE(soff[bb], soff[bb + 1])
                }
            }
        }
    }
    #undef SCAN_RANGE

    // ---- Phase 3: gather 4 channels (R is 16 KB, L2-resident) ----
    const float* Rb = R   + b * (4 * NPTS);
    float*       ob = out + b * (4 * 65536);
    #pragma unroll
    for (int c = 0; c < 4; ++c)
        ob[c * 65536 + cell] = __ldg(&Rb[c * NPTS + bi]);
}

extern "C" void kernel_launch(void* const* d_in, const int* in_sizes, int n_in,
                              void* d_out, int out_size) {
    const float* R  = (const float*)d_in[0];   // [2,4,1024]
    const float* XY = (const float*)d_in[1];   // [2,2,1024]
    float* out = (float*)d_out;                // [2,4,256,256]

    nn_fused<<<512, 256>>>(XY, R, out);
}